// round 17
// baseline (speedup 1.0000x reference)
#include <cuda_runtime.h>
#include <cuda_bf16.h>
#include <cstdint>

// Problem constants
#define VOCAB    100000
#define EMBED    128
#define BATCH    64
#define SEQLEN   2048
#define NCHUNK   16
#define CHUNK    (SEQLEN / NCHUNK)   // 128 tokens per block
#define LDGROWS  80                  // rows gathered via LDG path (5/8)
#define TMAROWS  48                  // rows gathered via TMA-bulk path (3/8)

// Device scratch (zero-initialized at load; every execution restores the
// all-zero invariant, so graph replays are deterministic).
__device__ float g_sums[BATCH * EMBED];
__device__ int   g_count[BATCH];

// ---- mbarrier / bulk-async helpers (validated in the passing R9 kernel) ----
__device__ __forceinline__ void mbar_init(uint32_t mbar, uint32_t count) {
    asm volatile("mbarrier.init.shared.b64 [%0], %1;" :: "r"(mbar), "r"(count) : "memory");
}
__device__ __forceinline__ void mbar_expect_tx(uint32_t mbar, uint32_t bytes) {
    asm volatile("mbarrier.arrive.expect_tx.shared.b64 _, [%0], %1;"
                 :: "r"(mbar), "r"(bytes) : "memory");
}
__device__ __forceinline__ void mbar_wait(uint32_t mbar, uint32_t parity) {
    asm volatile(
        "{\n\t"
        ".reg .pred P;\n\t"
        "WAIT_%=:\n\t"
        "mbarrier.try_wait.parity.acquire.cta.shared::cta.b64 P, [%0], %1, 0x989680;\n\t"
        "@P bra.uni DONE_%=;\n\t"
        "bra.uni WAIT_%=;\n\t"
        "DONE_%=:\n\t"
        "}"
        :: "r"(mbar), "r"(parity) : "memory");
}
__device__ __forceinline__ void bulk_g2s(uint32_t smem_dst, const void* gmem_src,
                                         uint32_t bytes, uint32_t mbar) {
    asm volatile(
        "cp.async.bulk.shared::cta.global.mbarrier::complete_tx::bytes "
        "[%0], [%1], %2, [%3];"
        :: "r"(smem_dst), "l"(gmem_src), "r"(bytes), "r"(mbar) : "memory");
}

// ---------------------------------------------------------------------------
// Single fused kernel. grid = (NCHUNK, BATCH) = (16, 64) = 1024 blocks x 128.
//
// Hybrid dual-path gather: the warm-L2 steady state delivers only ~5.3 TB/s
// because the SM-level LDG outstanding-miss cap (~37 lines/SM) binds, while
// the LTS itself has ~2x headroom. TMA-bulk requests are tracked by the TMA
// engine, NOT the L1TEX miss structures, so running both paths concurrently
// on disjoint rows adds their in-flight budgets:
//   rows [80..128): issued as 48 independent 512B cp.async.bulk into a 24KB
//                   smem tile (one mbarrier, expect_tx=24576) BEFORE the LDG
//                   work, consumed after it;
//   rows [0..80):   the proven R12 prefetch + 8-deep-batch LDG path.
// No inter-block waits; finalize via monotonic counter (deadlock-free).
// ---------------------------------------------------------------------------
__global__ __launch_bounds__(128, 8) void cbow_fused_kernel(
    const void* __restrict__ xraw,     // [BATCH, SEQLEN] token ids (int64 or int32)
    const float* __restrict__ emb,     // [VOCAB, EMBED] f32
    float* __restrict__ out)           // [BATCH, 4, EMBED] f32
{
    __shared__ float4 tile[TMAROWS][32];   // 24 KB TMA landing tile
    __shared__ int    toks[CHUNK];
    __shared__ float4 part[128];
    __shared__ unsigned long long mbar_storage;
    __shared__ int    s_is64;
    __shared__ int    s_last;

    const int b    = blockIdx.y;
    const int base = blockIdx.x * CHUNK;
    const int tid  = threadIdx.x;
    const int c    = tid & 31;   // float4 column within the 128-float row
    const int gph  = tid >> 5;   // row phase (0..3)

    const uint32_t mbar = (uint32_t)__cvta_generic_to_shared(&mbar_storage);
    const uint32_t tile_base = (uint32_t)__cvta_generic_to_shared(&tile[0][0]);

    // ---- Phase 0: dtype detection (warp 0) + mbarrier init ----
    if (tid < 32) {
        const long long v = ((const long long*)xraw)[tid];  // first 256B safe both dtypes
        const unsigned bad = __ballot_sync(0xFFFFFFFFu, v < 0 || v >= VOCAB);
        if (tid == 0) s_is64 = (bad == 0u);
    }
    if (tid == 0) mbar_init(mbar, 1);
    __syncthreads();
    const int is64 = s_is64;

    // ---- Phase 1: stage this chunk's 128 token ids (clamped int32) ----
    {
        const int idx = b * SEQLEN + base + tid;
        long long v = is64 ? ((const long long*)xraw)[idx]
                           : (long long)((const int*)xraw)[idx];
        if (v < 0) v = 0;
        if (v >= VOCAB) v = VOCAB - 1;
        toks[tid] = (int)v;
    }
    // expect_tx must be posted before any bulk completion can land.
    __syncthreads();
    if (tid == 0) mbar_expect_tx(mbar, TMAROWS * 512u);
    __syncthreads();

    // ---- Phase 2a: launch the TMA-bulk half (rows 80..127) ----
    if (tid < TMAROWS) {
        const int tok = toks[LDGROWS + tid];
        bulk_g2s(tile_base + (uint32_t)tid * 512u,
                 (const char*)emb + (size_t)tok * 512u, 512u, mbar);
    }

    // ---- Phase 2b: LDG half (rows 0..79), prefetch-decoupled, 8-deep ----
    // Thread (gph, c) owns rows t = gph + 4k, k = 0..19.
    #pragma unroll
    for (int t = gph; t < LDGROWS; t += 4) {
        const float4* p =
            reinterpret_cast<const float4*>(emb + (size_t)toks[t] * EMBED) + c;
        asm volatile("prefetch.global.L2 [%0];" :: "l"(p));
    }

    float4 acc0 = make_float4(0.f, 0.f, 0.f, 0.f);
    float4 acc1 = make_float4(0.f, 0.f, 0.f, 0.f);
    // 2 rounds of 8 + 1 round of 4 = 20 loads.
    #pragma unroll
    for (int round = 0; round < 2; round++) {
        float4 v[8];
        #pragma unroll
        for (int j = 0; j < 8; j++) {
            const int t = gph + (round * 8 + j) * 4;
            v[j] = __ldg(
                reinterpret_cast<const float4*>(emb + (size_t)toks[t] * EMBED) + c);
        }
        #pragma unroll
        for (int j = 0; j < 8; j += 2) {
            acc0.x += v[j].x;     acc0.y += v[j].y;
            acc0.z += v[j].z;     acc0.w += v[j].w;
            acc1.x += v[j + 1].x; acc1.y += v[j + 1].y;
            acc1.z += v[j + 1].z; acc1.w += v[j + 1].w;
        }
    }
    {
        float4 v[4];
        #pragma unroll
        for (int j = 0; j < 4; j++) {
            const int t = gph + (16 + j) * 4;
            v[j] = __ldg(
                reinterpret_cast<const float4*>(emb + (size_t)toks[t] * EMBED) + c);
        }
        acc0.x += v[0].x + v[2].x; acc0.y += v[0].y + v[2].y;
        acc0.z += v[0].z + v[2].z; acc0.w += v[0].w + v[2].w;
        acc1.x += v[1].x + v[3].x; acc1.y += v[1].y + v[3].y;
        acc1.z += v[1].z + v[3].z; acc1.w += v[1].w + v[3].w;
    }

    // ---- Phase 2c: consume the TMA tile (rows r = gph + 4k, k = 0..11) ----
    mbar_wait(mbar, 0u);
    #pragma unroll
    for (int k = 0; k < TMAROWS / 4; k += 2) {
        const float4 v0 = tile[gph + 4 * k][c];
        const float4 v1 = tile[gph + 4 * (k + 1)][c];
        acc0.x += v0.x; acc0.y += v0.y; acc0.z += v0.z; acc0.w += v0.w;
        acc1.x += v1.x; acc1.y += v1.y; acc1.z += v1.z; acc1.w += v1.w;
    }

    part[tid] = make_float4(acc0.x + acc1.x, acc0.y + acc1.y,
                            acc0.z + acc1.z, acc0.w + acc1.w);
    __syncthreads();

    // ---- Phase 3: reduce the 4 row phases, atomic into per-batch sum ----
    if (gph == 0) {
        const float4 p0 = part[c];
        const float4 p1 = part[32 + c];
        const float4 p2 = part[64 + c];
        const float4 p3 = part[96 + c];
        float* dst = &g_sums[b * EMBED + c * 4];
        atomicAdd(dst + 0, p0.x + p1.x + p2.x + p3.x);
        atomicAdd(dst + 1, p0.y + p1.y + p2.y + p3.y);
        atomicAdd(dst + 2, p0.z + p1.z + p2.z + p3.z);
        atomicAdd(dst + 3, p0.w + p1.w + p2.w + p3.w);
    }

    __threadfence();
    __syncthreads();
    if (tid == 0) {
        const int old = atomicAdd(&g_count[b], 1);
        s_last = (old == NCHUNK - 1);
    }
    __syncthreads();

    // ---- Phase 4: last block of this batch finalizes ----
    // Output [B, 4, E], offsets [-1, -2, +1, +2]:
    //   off -1: S - emb[x[L-1]]               + 1*emb[0]
    //   off -2: S - emb[x[L-1]] - emb[x[L-2]] + 2*emb[0]
    //   off +1: S - emb[x[0]]                 + 1*emb[0]
    //   off +2: S - emb[x[0]]   - emb[x[1]]   + 2*emb[0]
    if (s_last) {
        const int e = tid;
        const float S = *(volatile float*)&g_sums[b * EMBED + e];

        long long tf0, tf1, tl0, tl1;
        if (is64) {
            const long long* x64 = (const long long*)xraw;
            tf0 = x64[(size_t)b * SEQLEN + 0];
            tf1 = x64[(size_t)b * SEQLEN + 1];
            tl1 = x64[(size_t)b * SEQLEN + (SEQLEN - 2)];
            tl0 = x64[(size_t)b * SEQLEN + (SEQLEN - 1)];
        } else {
            const int* x32 = (const int*)xraw;
            tf0 = x32[(size_t)b * SEQLEN + 0];
            tf1 = x32[(size_t)b * SEQLEN + 1];
            tl1 = x32[(size_t)b * SEQLEN + (SEQLEN - 2)];
            tl0 = x32[(size_t)b * SEQLEN + (SEQLEN - 1)];
        }
        if (tf0 < 0) tf0 = 0; if (tf0 >= VOCAB) tf0 = VOCAB - 1;
        if (tf1 < 0) tf1 = 0; if (tf1 >= VOCAB) tf1 = VOCAB - 1;
        if (tl0 < 0) tl0 = 0; if (tl0 >= VOCAB) tl0 = VOCAB - 1;
        if (tl1 < 0) tl1 = 0; if (tl1 >= VOCAB) tl1 = VOCAB - 1;

        const float e0 = emb[e];  // emb[token 0][e]
        const float f0 = emb[(size_t)tf0 * EMBED + e];
        const float f1 = emb[(size_t)tf1 * EMBED + e];
        const float l0 = emb[(size_t)tl0 * EMBED + e];
        const float l1 = emb[(size_t)tl1 * EMBED + e];

        float* o = out + (size_t)b * 4 * EMBED;
        o[0 * EMBED + e] = S - l0 + e0;                  // offset -1
        o[1 * EMBED + e] = S - l0 - l1 + 2.0f * e0;      // offset -2
        o[2 * EMBED + e] = S - f0 + e0;                  // offset +1
        o[3 * EMBED + e] = S - f0 - f1 + 2.0f * e0;      // offset +2

        // Restore the zero-invariant for the next graph replay.
        g_sums[b * EMBED + e] = 0.0f;
        if (tid == 0) g_count[b] = 0;
    }
}

// ---------------------------------------------------------------------------
// Launch. Input order resolved from element counts:
//   x   : BATCH*SEQLEN = 131072 elements
//   emb : VOCAB*EMBED  = 12800000 elements
// ---------------------------------------------------------------------------
extern "C" void kernel_launch(void* const* d_in, const int* in_sizes, int n_in,
                              void* d_out, int out_size) {
    int ix = 0, ie = 1;
    if (in_sizes[0] != BATCH * SEQLEN) { ix = 1; ie = 0; }

    const void*  x   = d_in[ix];
    const float* emb = (const float*)d_in[ie];
    float*       out = (float*)d_out;

    dim3 grid(NCHUNK, BATCH);
    cbow_fused_kernel<<<grid, 128>>>(x, emb, out);
}